// round 10
// baseline (speedup 1.0000x reference)
#include <cuda_runtime.h>
#include <cuda_bf16.h>
#include <math.h>

#define N_NODES 50000
#define N_EDGES 800000
#define F_IN    300
#define HID     128
#define HEADS   4
#define NCLS    9

#define SCAN_B  256
#define SCAN_NB ((N_NODES + SCAN_B - 1) / SCAN_B)   // 196

// ---------------- scratch (device globals; no allocation) ----------------
__device__ int   g_is64;
__device__ int   g_deg[N_NODES];
__device__ int   g_cursor[N_NODES];
__device__ int   g_rowstart[N_NODES + 1];
__device__ int   g_adj_src[N_EDGES];
__device__ int   g_adj_dst[N_EDGES];
__device__ int   g_bsum[SCAN_NB];

__device__ float g_A[(size_t)N_NODES * HID];   // gemm output (pre-agg h)
__device__ float g_B[(size_t)N_NODES * HID];   // agg output (post-elu)
__device__ float g_as[(size_t)N_NODES * HEADS];
__device__ float g_ad[(size_t)N_NODES * HEADS];
__device__ float g_w[(size_t)N_EDGES * HEADS]; // per-edge softmax numerators
__device__ float g_w3[N_EDGES];
__device__ float g_h3[(size_t)N_NODES * 12];   // layer3 h padded to 12
__device__ float g_a3s[N_NODES];
__device__ float g_a3d[N_NODES];

// ---------------- helpers ----------------
__device__ __forceinline__ unsigned f2tf32(float x) {
    unsigned r;
    asm("cvt.rna.tf32.f32 %0, %1;" : "=r"(r) : "f"(x));
    return r;
}

#define MMA_TF32(c, a, b0, b1)                                                        \
    asm volatile("mma.sync.aligned.m16n8k8.row.col.f32.tf32.tf32.f32 "                \
                 "{%0,%1,%2,%3}, {%4,%5,%6,%7}, {%8,%9}, {%0,%1,%2,%3};"              \
                 : "+f"((c)[0]), "+f"((c)[1]), "+f"((c)[2]), "+f"((c)[3])             \
                 : "r"((a)[0]), "r"((a)[1]), "r"((a)[2]), "r"((a)[3]),                \
                   "r"(b0), "r"(b1))

__device__ __forceinline__ int edge_src(const void* ei, int e, int is64) {
    if (is64) return (int)((const long long*)ei)[e];
    return ((const int*)ei)[e];
}
__device__ __forceinline__ int edge_dst(const void* ei, int e, int is64) {
    if (is64) return (int)((const long long*)ei)[N_EDGES + e];
    return ((const int*)ei)[N_EDGES + e];
}
__device__ __forceinline__ float lrelu_exp(float e) {
    e = (e > 0.f) ? e : 0.2f * e;
    return __expf(e);
}

// ---------------- CSR build ----------------
__global__ void zero_kernel(const void* ei) {
    int i = blockIdx.x * blockDim.x + threadIdx.x;
    if (i < N_NODES) g_deg[i] = 0;
    if (blockIdx.x == 0) {
        __shared__ int any;
        if (threadIdx.x == 0) any = 0;
        __syncthreads();
        const int* p = (const int*)ei;
        for (int k = threadIdx.x; k < 4096; k += 256)
            if (p[2 * k + 1] != 0) any = 1;
        __syncthreads();
        if (threadIdx.x == 0) g_is64 = (any == 0) ? 1 : 0;
    }
}

__global__ void count_kernel(const void* __restrict__ ei) {
    int e = blockIdx.x * blockDim.x + threadIdx.x;
    int is64 = g_is64;
    if (e < N_EDGES) {
        int dst = edge_dst(ei, e, is64);
        if ((unsigned)dst < (unsigned)N_NODES)
            atomicAdd(&g_deg[dst], 1);
    }
}

__global__ void scanA_kernel() {
    __shared__ int ws[8];
    int t = threadIdx.x, lane = t & 31, warp = t >> 5;
    int i = blockIdx.x * SCAN_B + t;
    int v = (i < N_NODES) ? g_deg[i] : 0;
    #pragma unroll
    for (int off = 16; off; off >>= 1) v += __shfl_xor_sync(0xffffffffu, v, off);
    if (lane == 0) ws[warp] = v;
    __syncthreads();
    if (t == 0) {
        int s = 0;
        #pragma unroll
        for (int w = 0; w < 8; w++) s += ws[w];
        g_bsum[blockIdx.x] = s;
    }
}

__global__ void scanB_kernel() {
    __shared__ int ws[8];
    int t = threadIdx.x, lane = t & 31, warp = t >> 5;
    int v = (t < SCAN_NB) ? g_bsum[t] : 0;
    int x = v;
    #pragma unroll
    for (int off = 1; off < 32; off <<= 1) {
        int y = __shfl_up_sync(0xffffffffu, x, off);
        if (lane >= off) x += y;
    }
    if (lane == 31) ws[warp] = x;
    __syncthreads();
    if (warp == 0 && lane < 8) {
        int wv = ws[lane];
        #pragma unroll
        for (int off = 1; off < 8; off <<= 1) {
            int y = __shfl_up_sync(0xffu, wv, off);
            if (lane >= off) wv += y;
        }
        ws[lane] = wv;
    }
    __syncthreads();
    int excl = x - v + ((warp > 0) ? ws[warp - 1] : 0);
    if (t < SCAN_NB) g_bsum[t] = excl;
}

__global__ void scanC_kernel() {
    __shared__ int ws[8];
    int t = threadIdx.x, lane = t & 31, warp = t >> 5;
    int i = blockIdx.x * SCAN_B + t;
    int v = (i < N_NODES) ? g_deg[i] : 0;
    int x = v;
    #pragma unroll
    for (int off = 1; off < 32; off <<= 1) {
        int y = __shfl_up_sync(0xffffffffu, x, off);
        if (lane >= off) x += y;
    }
    if (lane == 31) ws[warp] = x;
    __syncthreads();
    if (warp == 0 && lane < 8) {
        int wv = ws[lane];
        #pragma unroll
        for (int off = 1; off < 8; off <<= 1) {
            int y = __shfl_up_sync(0xffu, wv, off);
            if (lane >= off) wv += y;
        }
        ws[lane] = wv;
    }
    __syncthreads();
    int incl = x + ((warp > 0) ? ws[warp - 1] : 0) + g_bsum[blockIdx.x];
    if (i < N_NODES) {
        g_rowstart[i + 1] = incl;
        g_cursor[i] = incl - v;
    }
    if (i == 0) g_rowstart[0] = 0;
}

__global__ void fill_kernel(const void* __restrict__ ei) {
    int e = blockIdx.x * blockDim.x + threadIdx.x;
    int is64 = g_is64;
    if (e < N_EDGES) {
        int dst = edge_dst(ei, e, is64);
        int src = edge_src(ei, e, is64);
        if ((unsigned)dst < (unsigned)N_NODES &&
            (unsigned)src < (unsigned)N_NODES) {
            int slot = atomicAdd(&g_cursor[dst], 1);
            if ((unsigned)slot < (unsigned)N_EDGES) {
                g_adj_src[slot] = src;
                g_adj_dst[slot] = dst;
            }
        }
    }
}

// ---------------- edge-parallel softmax numerators ----------------
__global__ void weight_kernel() {
    int e = blockIdx.x * blockDim.x + threadIdx.x;
    if (e >= N_EDGES) return;
    int src = g_adj_src[e];
    int dst = g_adj_dst[e];
    float4 s = *(const float4*)&g_as[src * HEADS];
    float4 d = *(const float4*)&g_ad[dst * HEADS];
    float4 w;
    w.x = lrelu_exp(s.x + d.x);
    w.y = lrelu_exp(s.y + d.y);
    w.z = lrelu_exp(s.z + d.z);
    w.w = lrelu_exp(s.w + d.w);
    *(float4*)&g_w[(size_t)e * HEADS] = w;
}

__global__ void weight3_kernel() {
    int e = blockIdx.x * blockDim.x + threadIdx.x;
    if (e >= N_EDGES) return;
    g_w3[e] = lrelu_exp(g_a3s[g_adj_src[e]] + g_a3d[g_adj_dst[e]]);
}

// ---------------- GEMM (tf32 split, tensor cores): C[M,128]=A[M,K]@W[K,128] ----------------
__global__ __launch_bounds__(256) void gemm_tf32_kernel(
        const float* __restrict__ Ain, const float* __restrict__ W, int M, int K,
        const float* __restrict__ att_s, const float* __restrict__ att_d) {
    __shared__ unsigned As_hi[16][132], As_lo[16][132];
    __shared__ unsigned Ws_hi[16][132], Ws_lo[16][132];
    const float* A = (Ain != nullptr) ? Ain : g_B;
    float* C = g_A;

    int t = threadIdx.x;
    int lane = t & 31, warp = t >> 5;
    int wr = warp >> 1;
    int wc = warp & 1;
    int row0 = blockIdx.x * 128;
    int q = lane & 3, g = lane >> 2;

    float acc[2][8][4];
    #pragma unroll
    for (int ma = 0; ma < 2; ma++)
        #pragma unroll
        for (int na = 0; na < 8; na++)
            #pragma unroll
            for (int r = 0; r < 4; r++) acc[ma][na][r] = 0.f;

    for (int k0 = 0; k0 < K; k0 += 16) {
        #pragma unroll
        for (int i = 0; i < 2; i++) {
            int row = t >> 1;
            int kg = (t & 1) * 2 + i;
            int gm = row0 + row;
            float v[4] = {0.f, 0.f, 0.f, 0.f};
            if (gm < M) {
                int kb = k0 + kg * 4;
                if (kb + 3 < K) {
                    float4 f = *(const float4*)&A[(size_t)gm * K + kb];
                    v[0] = f.x; v[1] = f.y; v[2] = f.z; v[3] = f.w;
                } else {
                    #pragma unroll
                    for (int j = 0; j < 4; j++)
                        if (kb + j < K) v[j] = A[(size_t)gm * K + kb + j];
                }
            }
            #pragma unroll
            for (int j = 0; j < 4; j++) {
                unsigned hi = f2tf32(v[j]);
                As_hi[kg * 4 + j][row] = hi;
                As_lo[kg * 4 + j][row] = f2tf32(v[j] - __uint_as_float(hi));
            }
        }
        #pragma unroll
        for (int i = 0; i < 2; i++) {
            int k = (t >> 5) + i * 8;
            int n = (t & 31) * 4;
            float v[4] = {0.f, 0.f, 0.f, 0.f};
            int gk = k0 + k;
            if (gk < K) {
                float4 f = *(const float4*)&W[(size_t)gk * 128 + n];
                v[0] = f.x; v[1] = f.y; v[2] = f.z; v[3] = f.w;
            }
            #pragma unroll
            for (int j = 0; j < 4; j++) {
                unsigned hi = f2tf32(v[j]);
                Ws_hi[k][n + j] = hi;
                Ws_lo[k][n + j] = f2tf32(v[j] - __uint_as_float(hi));
            }
        }
        __syncthreads();

        #pragma unroll
        for (int ks = 0; ks < 16; ks += 8) {
            unsigned ah[2][4], al[2][4];
            #pragma unroll
            for (int ma = 0; ma < 2; ma++) {
                int ra = wr * 32 + ma * 16 + g;
                int ka = ks + q;
                ah[ma][0] = As_hi[ka][ra];     ah[ma][1] = As_hi[ka][ra + 8];
                ah[ma][2] = As_hi[ka + 4][ra]; ah[ma][3] = As_hi[ka + 4][ra + 8];
                al[ma][0] = As_lo[ka][ra];     al[ma][1] = As_lo[ka][ra + 8];
                al[ma][2] = As_lo[ka + 4][ra]; al[ma][3] = As_lo[ka + 4][ra + 8];
            }
            #pragma unroll
            for (int na = 0; na < 8; na++) {
                int cb = wc * 64 + na * 8 + g;
                int kb = ks + q;
                unsigned bh0 = Ws_hi[kb][cb], bh1 = Ws_hi[kb + 4][cb];
                unsigned bl0 = Ws_lo[kb][cb], bl1 = Ws_lo[kb + 4][cb];
                #pragma unroll
                for (int ma = 0; ma < 2; ma++) {
                    MMA_TF32(acc[ma][na], ah[ma], bh0, bh1);
                    MMA_TF32(acc[ma][na], ah[ma], bl0, bl1);
                    MMA_TF32(acc[ma][na], al[ma], bh0, bh1);
                }
            }
        }
        __syncthreads();
    }

    #pragma unroll
    for (int ma = 0; ma < 2; ma++) {
        int gml = row0 + wr * 32 + ma * 16 + g;
        int gmh = gml + 8;
        #pragma unroll
        for (int na = 0; na < 8; na++) {
            int col = wc * 64 + na * 8 + 2 * q;
            if (gml < M)
                *(float2*)&C[(size_t)gml * 128 + col] = make_float2(acc[ma][na][0], acc[ma][na][1]);
            if (gmh < M)
                *(float2*)&C[(size_t)gmh * 128 + col] = make_float2(acc[ma][na][2], acc[ma][na][3]);
        }
    }

    if (att_s != nullptr) {
        #pragma unroll
        for (int ma = 0; ma < 2; ma++) {
            #pragma unroll
            for (int r = 0; r < 2; r++) {
                int gm = row0 + wr * 32 + ma * 16 + g + r * 8;
                #pragma unroll
                for (int hl = 0; hl < 2; hl++) {
                    float ps = 0.f, pd = 0.f;
                    #pragma unroll
                    for (int nn = 0; nn < 4; nn++) {
                        int na = hl * 4 + nn;
                        int col = wc * 64 + na * 8 + 2 * q;
                        float cA = acc[ma][na][r * 2 + 0];
                        float cB = acc[ma][na][r * 2 + 1];
                        ps += cA * att_s[col] + cB * att_s[col + 1];
                        pd += cA * att_d[col] + cB * att_d[col + 1];
                    }
                    ps += __shfl_xor_sync(0xffffffffu, ps, 1);
                    pd += __shfl_xor_sync(0xffffffffu, pd, 1);
                    ps += __shfl_xor_sync(0xffffffffu, ps, 2);
                    pd += __shfl_xor_sync(0xffffffffu, pd, 2);
                    if (q == 0 && gm < M) {
                        int head = wc * 2 + hl;
                        g_as[gm * HEADS + head] = ps;
                        g_ad[gm * HEADS + head] = pd;
                    }
                }
            }
        }
    }
}

// ---------------- aggregation: warp/node, float4 row gather (1 LDG.128/edge) --------
__global__ void agg128_kernel(const float* __restrict__ bias) {
    int t = threadIdx.x;
    int warp = t >> 5, lane = t & 31;
    int n = blockIdx.x * 8 + warp;
    if (n >= N_NODES) return;

    int s0 = g_rowstart[n], s1 = g_rowstart[n + 1];
    int head = lane >> 3;                  // lane*4 cols live in this head
    float4 acc = make_float4(0.f, 0.f, 0.f, 0.f);
    float wsum = 0.f;

    #pragma unroll 8
    for (int e = s0; e < s1; e++) {
        int src = g_adj_src[e];                                  // broadcast
        float4 w4 = *(const float4*)&g_w[(size_t)e * HEADS];     // broadcast
        float wh = (head == 0) ? w4.x : (head == 1) ? w4.y : (head == 2) ? w4.z : w4.w;
        float4 r = *(const float4*)&g_A[(size_t)src * 128 + lane * 4];  // 1 LDG.128
        acc.x += wh * r.x;
        acc.y += wh * r.y;
        acc.z += wh * r.z;
        acc.w += wh * r.w;
        wsum += wh;
    }

    float inv = (wsum > 0.f) ? 1.f / wsum : 0.f;
    float4 bi = *(const float4*)&bias[lane * 4];
    float o0 = acc.x * inv + bi.x;
    float o1 = acc.y * inv + bi.y;
    float o2 = acc.z * inv + bi.z;
    float o3 = acc.w * inv + bi.w;
    o0 = (o0 > 0.f) ? o0 : expm1f(o0);
    o1 = (o1 > 0.f) ? o1 : expm1f(o1);
    o2 = (o2 > 0.f) ? o2 : expm1f(o2);
    o3 = (o3 > 0.f) ? o3 : expm1f(o3);
    *(float4*)&g_B[(size_t)n * 128 + lane * 4] = make_float4(o0, o1, o2, o3);
}

// ---------------- layer 3 GEMM (128->9, padded 12) fused with attn dots ----------------
__global__ void gemm3_kernel(const float* __restrict__ W3, const float* __restrict__ as3,
                             const float* __restrict__ ad3) {
    __shared__ float Ws[128 * 12];
    int t = threadIdx.x;   // 256
    for (int i = t; i < 128 * 12; i += 256) {
        int k = i / 12, c = i % 12;
        Ws[i] = (c < NCLS) ? W3[k * NCLS + c] : 0.f;
    }
    __syncthreads();
    int warp = t >> 5, lane = t & 31;
    int n = blockIdx.x * 8 + warp;
    if (n >= N_NODES) return;
    float acc[12];
    #pragma unroll
    for (int c = 0; c < 12; c++) acc[c] = 0.f;
    const float* xr = g_B + (size_t)n * 128;
    #pragma unroll
    for (int kk = 0; kk < 4; kk++) {
        int k = lane + kk * 32;
        float xv = xr[k];
        #pragma unroll
        for (int c = 0; c < 12; c++) acc[c] += xv * Ws[k * 12 + c];
    }
    #pragma unroll
    for (int off = 16; off; off >>= 1)
        #pragma unroll
        for (int c = 0; c < 12; c++) acc[c] += __shfl_xor_sync(0xffffffffu, acc[c], off);
    if (lane == 0) {
        float s = 0.f, d = 0.f;
        #pragma unroll
        for (int c = 0; c < NCLS; c++) { s += acc[c] * as3[c]; d += acc[c] * ad3[c]; }
        g_a3s[n] = s;
        g_a3d[n] = d;
        float* hr = g_h3 + (size_t)n * 12;
        #pragma unroll
        for (int c = 0; c < 12; c++) hr[c] = acc[c];
    }
}

// ---------------- layer 3 aggregation + bias + elu + log_softmax ----------------
__global__ void agg3_kernel(const float* __restrict__ b3, float* __restrict__ out) {
    int t = threadIdx.x;
    int warp = t >> 5, lane = t & 31;
    int n = blockIdx.x * 8 + warp;
    if (n >= N_NODES) return;
    int s0 = g_rowstart[n], s1 = g_rowstart[n + 1];
    float4 A0 = make_float4(0, 0, 0, 0), A1 = A0, A2 = A0;
    float ws = 0.f;
    for (int i = s0 + lane; i < s1; i += 32) {
        int s = g_adj_src[i];
        float w = g_w3[i];
        ws += w;
        const float4* r = (const float4*)(g_h3 + (size_t)s * 12);
        float4 r0 = r[0], r1 = r[1], r2 = r[2];
        A0.x += w * r0.x; A0.y += w * r0.y; A0.z += w * r0.z; A0.w += w * r0.w;
        A1.x += w * r1.x; A1.y += w * r1.y; A1.z += w * r1.z; A1.w += w * r1.w;
        A2.x += w * r2.x;
    }
    #pragma unroll
    for (int off = 16; off; off >>= 1) {
        A0.x += __shfl_xor_sync(0xffffffffu, A0.x, off);
        A0.y += __shfl_xor_sync(0xffffffffu, A0.y, off);
        A0.z += __shfl_xor_sync(0xffffffffu, A0.z, off);
        A0.w += __shfl_xor_sync(0xffffffffu, A0.w, off);
        A1.x += __shfl_xor_sync(0xffffffffu, A1.x, off);
        A1.y += __shfl_xor_sync(0xffffffffu, A1.y, off);
        A1.z += __shfl_xor_sync(0xffffffffu, A1.z, off);
        A1.w += __shfl_xor_sync(0xffffffffu, A1.w, off);
        A2.x += __shfl_xor_sync(0xffffffffu, A2.x, off);
        ws += __shfl_xor_sync(0xffffffffu, ws, off);
    }
    if (lane == 0) {
        float inv = (ws > 0.f) ? 1.f / ws : 0.f;
        float v[9];
        v[0] = A0.x * inv; v[1] = A0.y * inv; v[2] = A0.z * inv; v[3] = A0.w * inv;
        v[4] = A1.x * inv; v[5] = A1.y * inv; v[6] = A1.z * inv; v[7] = A1.w * inv;
        v[8] = A2.x * inv;
        float m = -1e30f;
        #pragma unroll
        for (int c = 0; c < 9; c++) {
            v[c] += b3[c];
            v[c] = (v[c] > 0.f) ? v[c] : expm1f(v[c]);
            m = fmaxf(m, v[c]);
        }
        float se = 0.f;
        #pragma unroll
        for (int c = 0; c < 9; c++) se += __expf(v[c] - m);
        float l = logf(se);
        float* o = out + (size_t)n * 9;
        #pragma unroll
        for (int c = 0; c < 9; c++) o[c] = v[c] - m - l;
    }
}

// ---------------- launch ----------------
extern "C" void kernel_launch(void* const* d_in, const int* in_sizes, int n_in,
                              void* d_out, int out_size) {
    const float* x   = (const float*)d_in[0];
    const void*  ei  = d_in[1];
    const float* W1  = (const float*)d_in[2];
    const float* as1 = (const float*)d_in[3];
    const float* ad1 = (const float*)d_in[4];
    const float* b1  = (const float*)d_in[5];
    const float* W2  = (const float*)d_in[6];
    const float* as2 = (const float*)d_in[7];
    const float* ad2 = (const float*)d_in[8];
    const float* b2  = (const float*)d_in[9];
    const float* W3  = (const float*)d_in[10];
    const float* as3 = (const float*)d_in[11];
    const float* ad3 = (const float*)d_in[12];
    const float* b3  = (const float*)d_in[13];
    float* out = (float*)d_out;

    const int EB = (N_EDGES + 255) / 256;
    const int WB = (N_NODES + 7) / 8;        // warp-per-node grids
    const int GB = (N_NODES + 127) / 128;    // gemm tiles (128 rows)

    // CSR build
    zero_kernel<<<SCAN_NB, 256>>>(ei);
    count_kernel<<<EB, 256>>>(ei);
    scanA_kernel<<<SCAN_NB, SCAN_B>>>();
    scanB_kernel<<<1, 256>>>();
    scanC_kernel<<<SCAN_NB, SCAN_B>>>();
    fill_kernel<<<EB, 256>>>(ei);

    // layer 1
    gemm_tf32_kernel<<<GB, 256>>>(x, W1, N_NODES, F_IN, as1, ad1);
    weight_kernel<<<EB, 256>>>();
    agg128_kernel<<<WB, 256>>>(b1);

    // layer 2
    gemm_tf32_kernel<<<GB, 256>>>(nullptr, W2, N_NODES, HID, as2, ad2);
    weight_kernel<<<EB, 256>>>();
    agg128_kernel<<<WB, 256>>>(b2);

    // layer 3
    gemm3_kernel<<<WB, 256>>>(W3, as3, ad3);
    weight3_kernel<<<EB, 256>>>();
    agg3_kernel<<<WB, 256>>>(b3, out);
}